// round 11
// baseline (speedup 1.0000x reference)
#include <cuda_runtime.h>
#include <math.h>
#include <cstdint>

#define B_    8
#define N_    512
#define KN    128
#define ATOMS 4096
#define DRDIM 1600
#define F0    240
#define NTAB  512
#define SMAXF 1.3335f

// ---------------- scratch ----------------
__device__ float g_B [ATOMS * 400];   // tmpB [atom][f*100+h]
__device__ float g_H1[ATOMS * F0];
__device__ float g_H2[ATOMS * F0];
__device__ float g_tab[(NTAB + 1) * 100];
__device__ float g_WT1[F0 * DRDIM];   // fw0^T  [240][1600]
__device__ float g_WT2[F0 * F0];
__device__ float g_WT3[F0 * F0];

__device__ __forceinline__ float tanhfast(float x) {
    float e = __expf(2.0f * x);
    return 1.0f - __fdividef(2.0f, e + 1.0f);
}

__device__ __forceinline__ void split_tf32(float v, float& hi, float& lo) {
    asm("cvt.rna.tf32.f32 %0, %1;" : "=f"(hi) : "f"(v));
    float r = v - hi;
    asm("cvt.rna.tf32.f32 %0, %1;" : "=f"(lo) : "f"(r));
}

// m16n8k8 tf32 mma: D += A*B
__device__ __forceinline__ void mma8(float* d, const uint32_t* a,
                                     uint32_t b0, uint32_t b1) {
    asm volatile(
        "mma.sync.aligned.m16n8k8.row.col.f32.tf32.tf32.f32 "
        "{%0,%1,%2,%3}, {%4,%5,%6,%7}, {%8,%9}, {%0,%1,%2,%3};"
        : "+f"(d[0]), "+f"(d[1]), "+f"(d[2]), "+f"(d[3])
        : "r"(a[0]), "r"(a[1]), "r"(a[2]), "r"(a[3]), "r"(b0), "r"(b1));
}

// smem float offsets
#define SOA(buf, part) (((buf) * 2 + (part)) * 640)            // 32x20 each
#define SOB(buf, part) (2560 + ((buf) * 2 + (part)) * 4800)    // 240x20 each
#define SOBIAS         21760
#define SOFW3          22000                                   // 240 (EI only)
#define SOTB           22240                                   // 32 x 404 (FUSED only)
#define STBS           404
#define SOE            2560                                    // 32 x 242 (EI epi, reuses B)
#define SES            242
#define SMF_G23        22240
#define SMF_G1         (22240 + 32 * STBS)
#define SMB_G23        (SMF_G23 * 4)
#define SMB_G1         (SMF_G1 * 4)

// ====== tf32 mma.sync GEMM: C[4096,240] = tanh(A @ WT^T + bias) ======
// 192 threads = 6 warps: wm in {0,1}, wn in {0,1,2}. BM=32, BK=16.
// FUSED:   A synthesized per-tile from tmpB (rank-4 DR), K=1600.
// FUSE_EI: epilogue keeps H3 tile in smem and emits Ei directly.
template<bool FUSED, bool FUSE_EI>
__global__ __launch_bounds__(192) void mma_gemm(
    const float* __restrict__ A, const float* __restrict__ WT,
    const float* __restrict__ bias, float* __restrict__ C, int K,
    const float* __restrict__ fw3, const float* __restrict__ fb3,
    float* __restrict__ out)
{
    extern __shared__ float smf[];
    const int tid  = threadIdx.x;
    const int lane = tid & 31;
    const int wid  = tid >> 5;
    const int wm   = wid & 1;
    const int wn   = wid >> 1;        // 0..2
    const int gid  = lane >> 2;
    const int tig  = lane & 3;
    const int bm   = blockIdx.x * 32;
    const int T    = K / 16;

    for (int i = tid; i < F0; i += 192) smf[SOBIAS + i] = bias[i];
    if (FUSE_EI)
        for (int i = tid; i < F0; i += 192) smf[SOFW3 + i] = fw3[i];

    if (FUSED) {
        for (int i = tid; i < 3200; i += 192) {
            int at = i / 100, q = i - at * 100;
            float4 v = *(const float4*)(A + (size_t)(bm + at) * 400 + q * 4);
            *(float4*)(smf + SOTB + at * STBS + q * 4) = v;
        }
    }

    float acc[10][4];
#pragma unroll
    for (int f = 0; f < 10; f++)
#pragma unroll
        for (int j = 0; j < 4; j++) acc[f][j] = 0.0f;

    const int ar = tid >> 2, ac = tid & 3;
    float4 av;
    float4 bv[5];

    auto ldg_tile = [&](int kk0) {
        if (!FUSED && tid < 128)
            av = *(const float4*)(A + (size_t)(bm + ar) * K + kk0 + ac * 4);
#pragma unroll
        for (int j = 0; j < 5; j++) {
            int i = tid + j * 192;
            int n = i >> 2, c = i & 3;
            bv[j] = *(const float4*)(WT + (size_t)n * K + kk0 + c * 4);
        }
    };
    auto sts_tile = [&](int buf, int kk0) {
        float4 h, l;
        if (tid < 128) {
            if (FUSED) {
                const float* row = smf + SOTB + ar * STBS;
                float vv[4];
#pragma unroll
                for (int j = 0; j < 4; j++) {
                    int c = kk0 + ac * 4 + j;
                    int m = c / 100, hh = c - m * 100;
                    vv[j] = row[m]       * row[hh]
                          + row[100 + m] * row[100 + hh]
                          + row[200 + m] * row[200 + hh]
                          + row[300 + m] * row[300 + hh];
                }
                av = make_float4(vv[0], vv[1], vv[2], vv[3]);
            }
            split_tf32(av.x, h.x, l.x); split_tf32(av.y, h.y, l.y);
            split_tf32(av.z, h.z, l.z); split_tf32(av.w, h.w, l.w);
            *(float4*)(smf + SOA(buf, 0) + ar * 20 + ac * 4) = h;
            *(float4*)(smf + SOA(buf, 1) + ar * 20 + ac * 4) = l;
        }
#pragma unroll
        for (int j = 0; j < 5; j++) {
            int i = tid + j * 192;
            int n = i >> 2, c = i & 3;
            split_tf32(bv[j].x, h.x, l.x); split_tf32(bv[j].y, h.y, l.y);
            split_tf32(bv[j].z, h.z, l.z); split_tf32(bv[j].w, h.w, l.w);
            *(float4*)(smf + SOB(buf, 0) + n * 20 + c * 4) = h;
            *(float4*)(smf + SOB(buf, 1) + n * 20 + c * 4) = l;
        }
    };

    ldg_tile(0);
    if (FUSED || FUSE_EI) __syncthreads();
    sts_tile(0, 0);
    __syncthreads();

    for (int t = 0; t < T; t++) {
        const int buf = t & 1;
        if (t + 1 < T) ldg_tile((t + 1) * 16);

        const float* pAh = smf + SOA(buf, 0);
        const float* pAl = smf + SOA(buf, 1);
        const float* pBh = smf + SOB(buf, 0);
        const float* pBl = smf + SOB(buf, 1);
        const int ra = wm * 16 + gid;
#pragma unroll
        for (int ks = 0; ks < 2; ks++) {
            const int k0 = ks * 8;
            uint32_t ah[4], al[4];
            ah[0] = __float_as_uint(pAh[ ra      * 20 + k0 + tig]);
            ah[1] = __float_as_uint(pAh[(ra + 8) * 20 + k0 + tig]);
            ah[2] = __float_as_uint(pAh[ ra      * 20 + k0 + tig + 4]);
            ah[3] = __float_as_uint(pAh[(ra + 8) * 20 + k0 + tig + 4]);
            al[0] = __float_as_uint(pAl[ ra      * 20 + k0 + tig]);
            al[1] = __float_as_uint(pAl[(ra + 8) * 20 + k0 + tig]);
            al[2] = __float_as_uint(pAl[ ra      * 20 + k0 + tig + 4]);
            al[3] = __float_as_uint(pAl[(ra + 8) * 20 + k0 + tig + 4]);
#pragma unroll
            for (int nf = 0; nf < 10; nf++) {
                const int rb = wn * 80 + nf * 8 + gid;
                uint32_t bh0 = __float_as_uint(pBh[rb * 20 + k0 + tig]);
                uint32_t bh1 = __float_as_uint(pBh[rb * 20 + k0 + tig + 4]);
                uint32_t bl0 = __float_as_uint(pBl[rb * 20 + k0 + tig]);
                uint32_t bl1 = __float_as_uint(pBl[rb * 20 + k0 + tig + 4]);
                mma8(acc[nf], ah, bh0, bh1);
                mma8(acc[nf], ah, bl0, bl1);
                mma8(acc[nf], al, bh0, bh1);
            }
        }
        if (t + 1 < T) sts_tile(1 - buf, (t + 1) * 16);
        __syncthreads();
    }

    // epilogue
    const int lr0 = wm * 16 + gid;
#pragma unroll
    for (int nf = 0; nf < 10; nf++) {
        const int col = wn * 80 + nf * 8 + tig * 2;
        const float b0 = smf[SOBIAS + col];
        const float b1 = smf[SOBIAS + col + 1];
        float2 v0, v1;
        v0.x = tanhfast(acc[nf][0] + b0);
        v0.y = tanhfast(acc[nf][1] + b1);
        v1.x = tanhfast(acc[nf][2] + b0);
        v1.y = tanhfast(acc[nf][3] + b1);
        if (FUSE_EI) {
            *(float2*)(smf + SOE + lr0 * SES + col)       = v0;
            *(float2*)(smf + SOE + (lr0 + 8) * SES + col) = v1;
        } else {
            *(float2*)(C + (size_t)(bm + lr0) * F0 + col)     = v0;
            *(float2*)(C + (size_t)(bm + lr0 + 8) * F0 + col) = v1;
        }
    }

    if (FUSE_EI) {
        __syncthreads();
        const float fb3v = __ldg(fb3);
        for (int r = wid; r < 32; r += 6) {
            const float* row = smf + SOE + r * SES;
            float a = 0.0f;
#pragma unroll
            for (int i = lane; i < F0; i += 32)
                a = fmaf(row[i], smf[SOFW3 + i], a);
#pragma unroll
            for (int off = 16; off; off >>= 1)
                a += __shfl_xor_sync(0xFFFFFFFFu, a, off);
            if (lane == 0) out[8 + bm + r] = a + fb3v;
        }
    }
}

// ---------------- merged weight transpose: WT[N][K] = W[K][N] --------------
__global__ __launch_bounds__(256) void transpose_all_kernel(
    const float* __restrict__ fw0, const float* __restrict__ fw1,
    const float* __restrict__ fw2,
    float* __restrict__ wt1, float* __restrict__ wt2, float* __restrict__ wt3)
{
    __shared__ float t[32][33];
    const int z = blockIdx.z;
    const float* W = (z == 0) ? fw0 : (z == 1) ? fw1 : fw2;
    float* WT      = (z == 0) ? wt1 : (z == 1) ? wt2 : wt3;
    const int K    = (z == 0) ? DRDIM : F0;
    const int N    = F0;
    int k0 = blockIdx.x * 32, n0 = blockIdx.y * 32;
    if (k0 >= K) return;
    int x = threadIdx.x, y = threadIdx.y;
#pragma unroll
    for (int dy = 0; dy < 32; dy += 8) {
        int k = k0 + y + dy, n = n0 + x;
        t[y + dy][x] = (k < K && n < N) ? W[(size_t)k * N + n] : 0.0f;
    }
    __syncthreads();
#pragma unroll
    for (int dy = 0; dy < 32; dy += 8) {
        int n = n0 + y + dy, k = k0 + x;
        if (n < N && k < K) WT[(size_t)n * K + k] = t[x][y + dy];
    }
}

// ---------------- build G(S) table: 16 nodes per block ----------------
__global__ __launch_bounds__(128) void build_tab_kernel(
    const float* __restrict__ ew0, const float* __restrict__ eb0,
    const float* __restrict__ ew1, const float* __restrict__ eb1,
    const float* __restrict__ ew2, const float* __restrict__ eb2)
{
    __shared__ float sw1[25 * 50];
    __shared__ float sw2[50 * 100];
    __shared__ float sh1[25], sh2[50];

    const int tid = threadIdx.x;
    for (int k = tid; k < 1250; k += 128) sw1[k] = ew1[k];
    for (int k = tid; k < 5000; k += 128) sw2[k] = ew2[k];
    __syncthreads();

    for (int n = 0; n < 16; n++) {
        const int i = blockIdx.x * 16 + n;
        if (i > NTAB) break;
        const float S = (float)i * (SMAXF / (float)NTAB);
        if (tid < 25)
            sh1[tid] = tanhfast(fmaf(S, __ldg(&ew0[tid]), __ldg(&eb0[tid])));
        __syncthreads();
        if (tid < 50) {
            float a = __ldg(&eb1[tid]);
#pragma unroll
            for (int q = 0; q < 25; q++) a = fmaf(sh1[q], sw1[q * 50 + tid], a);
            sh2[tid] = tanhfast(a);
        }
        __syncthreads();
        if (tid < 100) {
            float g = __ldg(&eb2[tid]);
#pragma unroll
            for (int q = 0; q < 50; q++) g = fmaf(sh2[q], sw2[q * 100 + tid], g);
            g_tab[i * 100 + tid] = tanhfast(g);
        }
        __syncthreads();
    }
}

// ---------------- embed: geometry + table interp -> tmpB ----------------
__global__ __launch_bounds__(128) void embed_kernel(const float4* __restrict__ img)
{
    __shared__ float sRi[128 * 4];
    __shared__ float sG[128 * 21];
    __shared__ float sB[400];

    const int tid = threadIdx.x;
    const int atom = blockIdx.x;

    float4 p = img[atom * KN + tid];
    float R = p.x * p.x + p.y * p.y + p.z * p.z;
    bool mask = p.w > 0.0f;
    float S = 0.0f;
    if (R < 10.0f) {
        if (mask) S = 1.0f / R;
    } else if (R < 25.0f) {
        S = 0.5f * cosf(0.20943951023931953f * (R - 10.0f)) + 0.5f;
    }
    float coef = mask ? S / R : 0.0f;
    sRi[tid * 4 + 0] = S;
    sRi[tid * 4 + 1] = coef * p.x;
    sRi[tid * 4 + 2] = coef * p.y;
    sRi[tid * 4 + 3] = coef * p.z;

    float t = S * ((float)NTAB / SMAXF);
    int idx = (int)t;
    if (idx > NTAB - 1) idx = NTAB - 1;
    float frac = t - (float)idx;
    const float4* r0 = reinterpret_cast<const float4*>(g_tab + idx * 100);
    const float4* r1 = reinterpret_cast<const float4*>(g_tab + (idx + 1) * 100);
    __syncthreads();

#pragma unroll 1
    for (int chunk = 0; chunk < 5; chunk++) {
#pragma unroll
        for (int q = 0; q < 5; q++) {
            float4 a = __ldg(&r0[chunk * 5 + q]);
            float4 b = __ldg(&r1[chunk * 5 + q]);
            sG[tid * 21 + q * 4 + 0] = fmaf(frac, b.x - a.x, a.x);
            sG[tid * 21 + q * 4 + 1] = fmaf(frac, b.y - a.y, a.y);
            sG[tid * 21 + q * 4 + 2] = fmaf(frac, b.z - a.z, a.z);
            sG[tid * 21 + q * 4 + 3] = fmaf(frac, b.w - a.w, a.w);
        }
        __syncthreads();
        if (tid < 80) {
            int f = tid / 20, c = tid - f * 20;
            float a0 = 0.0f, a1 = 0.0f, a2 = 0.0f, a3 = 0.0f;
#pragma unroll 8
            for (int j = 0; j < 128; j += 4) {
                a0 = fmaf(sRi[((j + 0) << 2) + f], sG[(j + 0) * 21 + c], a0);
                a1 = fmaf(sRi[((j + 1) << 2) + f], sG[(j + 1) * 21 + c], a1);
                a2 = fmaf(sRi[((j + 2) << 2) + f], sG[(j + 2) * 21 + c], a2);
                a3 = fmaf(sRi[((j + 3) << 2) + f], sG[(j + 3) * 21 + c], a3);
            }
            sB[f * 100 + chunk * 20 + c] = (a0 + a1) + (a2 + a3);
        }
        __syncthreads();
    }

    for (int o = tid; o < 400; o += 128)
        g_B[atom * 400 + o] = sB[o];
}

// ---------------- Etot ----------------
__global__ __launch_bounds__(128) void etot_kernel(float* __restrict__ out)
{
    __shared__ float red[4];
    int b = blockIdx.x;
    int tid = threadIdx.x;
    float a = 0.0f;
    for (int i = tid; i < N_; i += 128) a += out[8 + b * N_ + i];
#pragma unroll
    for (int off = 16; off; off >>= 1) a += __shfl_xor_sync(0xFFFFFFFFu, a, off);
    if ((tid & 31) == 0) red[tid >> 5] = a;
    __syncthreads();
    if (tid == 0) out[b] = red[0] + red[1] + red[2] + red[3];
}

// ---------------- launch ----------------
extern "C" void kernel_launch(void* const* d_in, const int* in_sizes, int n_in,
                              void* d_out, int out_size)
{
    const float* img = (const float*)d_in[0];
    const float* ew0 = (const float*)d_in[1];
    const float* eb0 = (const float*)d_in[2];
    const float* ew1 = (const float*)d_in[3];
    const float* eb1 = (const float*)d_in[4];
    const float* ew2 = (const float*)d_in[5];
    const float* eb2 = (const float*)d_in[6];
    const float* fw0 = (const float*)d_in[7];
    const float* fb0 = (const float*)d_in[8];
    const float* fw1 = (const float*)d_in[9];
    const float* fb1 = (const float*)d_in[10];
    const float* fw2 = (const float*)d_in[11];
    const float* fb2 = (const float*)d_in[12];
    const float* fw3 = (const float*)d_in[13];
    const float* fb3 = (const float*)d_in[14];
    float* out = (float*)d_out;

    void *pB, *pH1, *pH2, *pWT1, *pWT2, *pWT3;
    cudaGetSymbolAddress(&pB,  g_B);
    cudaGetSymbolAddress(&pH1, g_H1);
    cudaGetSymbolAddress(&pH2, g_H2);
    cudaGetSymbolAddress(&pWT1, g_WT1);
    cudaGetSymbolAddress(&pWT2, g_WT2);
    cudaGetSymbolAddress(&pWT3, g_WT3);

    cudaFuncSetAttribute(mma_gemm<true, false>,
                         cudaFuncAttributeMaxDynamicSharedMemorySize, SMB_G1);
    cudaFuncSetAttribute(mma_gemm<false, false>,
                         cudaFuncAttributeMaxDynamicSharedMemorySize, SMB_G23);
    cudaFuncSetAttribute(mma_gemm<false, true>,
                         cudaFuncAttributeMaxDynamicSharedMemorySize, SMB_G23);

    transpose_all_kernel<<<dim3(50, 8, 3), dim3(32, 8)>>>(
        fw0, fw1, fw2, (float*)pWT1, (float*)pWT2, (float*)pWT3);
    build_tab_kernel<<<33, 128>>>(ew0, eb0, ew1, eb1, ew2, eb2);
    embed_kernel<<<ATOMS, 128>>>((const float4*)img);

    // launch index 3 (profiled slot): fused GEMM1
    mma_gemm<true, false><<<ATOMS / 32, 192, SMB_G1>>>(
        (const float*)pB, (const float*)pWT1, fb0, (float*)pH1, DRDIM,
        nullptr, nullptr, nullptr);
    mma_gemm<false, false><<<ATOMS / 32, 192, SMB_G23>>>(
        (const float*)pH1, (const float*)pWT2, fb1, (float*)pH2, F0,
        nullptr, nullptr, nullptr);
    mma_gemm<false, true><<<ATOMS / 32, 192, SMB_G23>>>(
        (const float*)pH2, (const float*)pWT3, fb2, nullptr, F0,
        fw3, fb3, out);

    etot_kernel<<<B_, 128>>>(out);
}

// round 14
// speedup vs baseline: 1.0307x; 1.0307x over previous
#include <cuda_runtime.h>
#include <math.h>
#include <cstdint>

#define B_    8
#define N_    512
#define KN    128
#define ATOMS 4096
#define DRDIM 1600
#define F0    240
#define NTAB  512
#define SMAXF 1.3335f

// ---------------- scratch ----------------
__device__ float g_B [ATOMS * 400];   // tmpB [atom][f*100+h]
__device__ float g_H1[ATOMS * F0];
__device__ float g_H2[ATOMS * F0];
__device__ float g_tab[(NTAB + 1) * 100];
__device__ float g_WT1[F0 * DRDIM];   // fw0^T  [240][1600]
__device__ float g_WT2[F0 * F0];
__device__ float g_WT3[F0 * F0];

__device__ __forceinline__ float tanhfast(float x) {
    float e = __expf(2.0f * x);
    return 1.0f - __fdividef(2.0f, e + 1.0f);
}

__device__ __forceinline__ void split_tf32(float v, float& hi, float& lo) {
    asm("cvt.rna.tf32.f32 %0, %1;" : "=f"(hi) : "f"(v));
    float r = v - hi;
    asm("cvt.rna.tf32.f32 %0, %1;" : "=f"(lo) : "f"(r));
}

// m16n8k8 tf32 mma: D += A*B
__device__ __forceinline__ void mma8(float* d, const uint32_t* a,
                                     uint32_t b0, uint32_t b1) {
    asm volatile(
        "mma.sync.aligned.m16n8k8.row.col.f32.tf32.tf32.f32 "
        "{%0,%1,%2,%3}, {%4,%5,%6,%7}, {%8,%9}, {%0,%1,%2,%3};"
        : "+f"(d[0]), "+f"(d[1]), "+f"(d[2]), "+f"(d[3])
        : "r"(a[0]), "r"(a[1]), "r"(a[2]), "r"(a[3]), "r"(b0), "r"(b1));
}

// smem float offsets
#define SOA(buf, part) (((buf) * 2 + (part)) * 640)            // 32x20 each
#define SOB(buf, part) (2560 + ((buf) * 2 + (part)) * 4800)    // 240x20 each
#define SOBIAS         21760
#define SOFW3          22000                                   // 240 (EI only)
#define SOTB           22240                                   // 32 x 404 (FUSED only)
#define STBS           404
#define SOE            2560                                    // 32 x 242 (EI epi, reuses B)
#define SES            242
#define SMF_G23        22240
#define SMF_G1         (22240 + 32 * STBS)
#define SMB_G23        (SMF_G23 * 4)
#define SMB_G1         (SMF_G1 * 4)

#define NT 384

// ====== tf32 mma.sync GEMM: C[4096,240] = tanh(A @ WT^T + bias) ======
// 384 threads = 12 warps: wm in {0,1} (16 rows), wn in {0..5} (40 cols, 5 frags).
// BM=32, BK=16. FUSED: A synthesized per-tile from tmpB (rank-4 DR), K=1600.
// FUSE_EI: epilogue keeps H3 tile in smem and emits Ei directly.
template<bool FUSED, bool FUSE_EI>
__global__ __launch_bounds__(NT) void mma_gemm(
    const float* __restrict__ A, const float* __restrict__ WT,
    const float* __restrict__ bias, float* __restrict__ C, int K,
    const float* __restrict__ fw3, const float* __restrict__ fb3,
    float* __restrict__ out)
{
    extern __shared__ float smf[];
    const int tid  = threadIdx.x;
    const int lane = tid & 31;
    const int wid  = tid >> 5;        // 0..11
    const int wm   = wid & 1;
    const int wn   = wid >> 1;        // 0..5
    const int gid  = lane >> 2;
    const int tig  = lane & 3;
    const int bm   = blockIdx.x * 32;
    const int T    = K / 16;

    for (int i = tid; i < F0; i += NT) smf[SOBIAS + i] = bias[i];
    if (FUSE_EI)
        for (int i = tid; i < F0; i += NT) smf[SOFW3 + i] = fw3[i];

    if (FUSED) {
        for (int i = tid; i < 3200; i += NT) {
            int at = i / 100, q = i - at * 100;
            float4 v = *(const float4*)(A + (size_t)(bm + at) * 400 + q * 4);
            *(float4*)(smf + SOTB + at * STBS + q * 4) = v;
        }
    }

    float acc[5][4];
#pragma unroll
    for (int f = 0; f < 5; f++)
#pragma unroll
        for (int j = 0; j < 4; j++) acc[f][j] = 0.0f;

    const int ar = tid >> 2, ac = tid & 3;     // A: threads 0..127
    float4 av;
    float4 bv[3];

    auto ldg_tile = [&](int kk0) {
        if (!FUSED && tid < 128)
            av = *(const float4*)(A + (size_t)(bm + ar) * K + kk0 + ac * 4);
#pragma unroll
        for (int j = 0; j < 3; j++) {
            int i = tid + j * NT;              // 960 total
            if (i < 960) {
                int n = i >> 2, c = i & 3;
                bv[j] = *(const float4*)(WT + (size_t)n * K + kk0 + c * 4);
            }
        }
    };
    auto sts_tile = [&](int buf, int kk0) {
        float4 h, l;
        if (tid < 128) {
            if (FUSED) {
                const float* row = smf + SOTB + ar * STBS;
                float vv[4];
#pragma unroll
                for (int j = 0; j < 4; j++) {
                    int c = kk0 + ac * 4 + j;
                    int m = c / 100, hh = c - m * 100;
                    vv[j] = row[m]       * row[hh]
                          + row[100 + m] * row[100 + hh]
                          + row[200 + m] * row[200 + hh]
                          + row[300 + m] * row[300 + hh];
                }
                av = make_float4(vv[0], vv[1], vv[2], vv[3]);
            }
            split_tf32(av.x, h.x, l.x); split_tf32(av.y, h.y, l.y);
            split_tf32(av.z, h.z, l.z); split_tf32(av.w, h.w, l.w);
            *(float4*)(smf + SOA(buf, 0) + ar * 20 + ac * 4) = h;
            *(float4*)(smf + SOA(buf, 1) + ar * 20 + ac * 4) = l;
        }
#pragma unroll
        for (int j = 0; j < 3; j++) {
            int i = tid + j * NT;
            if (i < 960) {
                int n = i >> 2, c = i & 3;
                split_tf32(bv[j].x, h.x, l.x); split_tf32(bv[j].y, h.y, l.y);
                split_tf32(bv[j].z, h.z, l.z); split_tf32(bv[j].w, h.w, l.w);
                *(float4*)(smf + SOB(buf, 0) + n * 20 + c * 4) = h;
                *(float4*)(smf + SOB(buf, 1) + n * 20 + c * 4) = l;
            }
        }
    };

    ldg_tile(0);
    if (FUSED || FUSE_EI) __syncthreads();
    sts_tile(0, 0);
    __syncthreads();

    for (int t = 0; t < T; t++) {
        const int buf = t & 1;
        if (t + 1 < T) ldg_tile((t + 1) * 16);

        const float* pAh = smf + SOA(buf, 0);
        const float* pAl = smf + SOA(buf, 1);
        const float* pBh = smf + SOB(buf, 0);
        const float* pBl = smf + SOB(buf, 1);
        const int ra = wm * 16 + gid;
#pragma unroll
        for (int ks = 0; ks < 2; ks++) {
            const int k0 = ks * 8;
            uint32_t ah[4], al[4];
            ah[0] = __float_as_uint(pAh[ ra      * 20 + k0 + tig]);
            ah[1] = __float_as_uint(pAh[(ra + 8) * 20 + k0 + tig]);
            ah[2] = __float_as_uint(pAh[ ra      * 20 + k0 + tig + 4]);
            ah[3] = __float_as_uint(pAh[(ra + 8) * 20 + k0 + tig + 4]);
            al[0] = __float_as_uint(pAl[ ra      * 20 + k0 + tig]);
            al[1] = __float_as_uint(pAl[(ra + 8) * 20 + k0 + tig]);
            al[2] = __float_as_uint(pAl[ ra      * 20 + k0 + tig + 4]);
            al[3] = __float_as_uint(pAl[(ra + 8) * 20 + k0 + tig + 4]);
#pragma unroll
            for (int nf = 0; nf < 5; nf++) {
                const int rb = wn * 40 + nf * 8 + gid;
                uint32_t bh0 = __float_as_uint(pBh[rb * 20 + k0 + tig]);
                uint32_t bh1 = __float_as_uint(pBh[rb * 20 + k0 + tig + 4]);
                uint32_t bl0 = __float_as_uint(pBl[rb * 20 + k0 + tig]);
                uint32_t bl1 = __float_as_uint(pBl[rb * 20 + k0 + tig + 4]);
                mma8(acc[nf], ah, bh0, bh1);
                mma8(acc[nf], ah, bl0, bl1);
                mma8(acc[nf], al, bh0, bh1);
            }
        }
        if (t + 1 < T) sts_tile(1 - buf, (t + 1) * 16);
        __syncthreads();
    }

    // epilogue
    const int lr0 = wm * 16 + gid;
#pragma unroll
    for (int nf = 0; nf < 5; nf++) {
        const int col = wn * 40 + nf * 8 + tig * 2;
        const float b0 = smf[SOBIAS + col];
        const float b1 = smf[SOBIAS + col + 1];
        float2 v0, v1;
        v0.x = tanhfast(acc[nf][0] + b0);
        v0.y = tanhfast(acc[nf][1] + b1);
        v1.x = tanhfast(acc[nf][2] + b0);
        v1.y = tanhfast(acc[nf][3] + b1);
        if (FUSE_EI) {
            *(float2*)(smf + SOE + lr0 * SES + col)       = v0;
            *(float2*)(smf + SOE + (lr0 + 8) * SES + col) = v1;
        } else {
            *(float2*)(C + (size_t)(bm + lr0) * F0 + col)     = v0;
            *(float2*)(C + (size_t)(bm + lr0 + 8) * F0 + col) = v1;
        }
    }

    if (FUSE_EI) {
        __syncthreads();
        const float fb3v = __ldg(fb3);
        for (int r = wid; r < 32; r += 12) {
            const float* row = smf + SOE + r * SES;
            float a = 0.0f;
#pragma unroll
            for (int i = lane; i < F0; i += 32)
                a = fmaf(row[i], smf[SOFW3 + i], a);
#pragma unroll
            for (int off = 16; off; off >>= 1)
                a += __shfl_xor_sync(0xFFFFFFFFu, a, off);
            if (lane == 0) out[8 + bm + r] = a + fb3v;
        }
    }
}

// ---------------- merged weight transpose: WT[N][K] = W[K][N] --------------
__global__ __launch_bounds__(256) void transpose_all_kernel(
    const float* __restrict__ fw0, const float* __restrict__ fw1,
    const float* __restrict__ fw2,
    float* __restrict__ wt1, float* __restrict__ wt2, float* __restrict__ wt3)
{
    __shared__ float t[32][33];
    const int z = blockIdx.z;
    const float* W = (z == 0) ? fw0 : (z == 1) ? fw1 : fw2;
    float* WT      = (z == 0) ? wt1 : (z == 1) ? wt2 : wt3;
    const int K    = (z == 0) ? DRDIM : F0;
    const int N    = F0;
    int k0 = blockIdx.x * 32, n0 = blockIdx.y * 32;
    if (k0 >= K) return;
    int x = threadIdx.x, y = threadIdx.y;
#pragma unroll
    for (int dy = 0; dy < 32; dy += 8) {
        int k = k0 + y + dy, n = n0 + x;
        t[y + dy][x] = (k < K && n < N) ? W[(size_t)k * N + n] : 0.0f;
    }
    __syncthreads();
#pragma unroll
    for (int dy = 0; dy < 32; dy += 8) {
        int n = n0 + y + dy, k = k0 + x;
        if (n < N && k < K) WT[(size_t)n * K + k] = t[x][y + dy];
    }
}

// ---------------- build G(S) table: 16 nodes per block ----------------
__global__ __launch_bounds__(128) void build_tab_kernel(
    const float* __restrict__ ew0, const float* __restrict__ eb0,
    const float* __restrict__ ew1, const float* __restrict__ eb1,
    const float* __restrict__ ew2, const float* __restrict__ eb2)
{
    __shared__ float sw1[25 * 50];
    __shared__ float sw2[50 * 100];
    __shared__ float sh1[25], sh2[50];

    const int tid = threadIdx.x;
    for (int k = tid; k < 1250; k += 128) sw1[k] = ew1[k];
    for (int k = tid; k < 5000; k += 128) sw2[k] = ew2[k];
    __syncthreads();

    for (int n = 0; n < 16; n++) {
        const int i = blockIdx.x * 16 + n;
        if (i > NTAB) break;
        const float S = (float)i * (SMAXF / (float)NTAB);
        if (tid < 25)
            sh1[tid] = tanhfast(fmaf(S, __ldg(&ew0[tid]), __ldg(&eb0[tid])));
        __syncthreads();
        if (tid < 50) {
            float a = __ldg(&eb1[tid]);
#pragma unroll
            for (int q = 0; q < 25; q++) a = fmaf(sh1[q], sw1[q * 50 + tid], a);
            sh2[tid] = tanhfast(a);
        }
        __syncthreads();
        if (tid < 100) {
            float g = __ldg(&eb2[tid]);
#pragma unroll
            for (int q = 0; q < 50; q++) g = fmaf(sh2[q], sw2[q * 100 + tid], g);
            g_tab[i * 100 + tid] = tanhfast(g);
        }
        __syncthreads();
    }
}

// ---------------- embed: geometry + table interp -> tmpB ----------------
__global__ __launch_bounds__(128) void embed_kernel(const float4* __restrict__ img)
{
    __shared__ float sRi[128 * 4];
    __shared__ float sG[128 * 21];
    __shared__ float sB[400];

    const int tid = threadIdx.x;
    const int atom = blockIdx.x;

    float4 p = img[atom * KN + tid];
    float R = p.x * p.x + p.y * p.y + p.z * p.z;
    bool mask = p.w > 0.0f;
    float S = 0.0f;
    if (R < 10.0f) {
        if (mask) S = 1.0f / R;
    } else if (R < 25.0f) {
        S = 0.5f * cosf(0.20943951023931953f * (R - 10.0f)) + 0.5f;
    }
    float coef = mask ? S / R : 0.0f;
    sRi[tid * 4 + 0] = S;
    sRi[tid * 4 + 1] = coef * p.x;
    sRi[tid * 4 + 2] = coef * p.y;
    sRi[tid * 4 + 3] = coef * p.z;

    float t = S * ((float)NTAB / SMAXF);
    int idx = (int)t;
    if (idx > NTAB - 1) idx = NTAB - 1;
    float frac = t - (float)idx;
    const float4* r0 = reinterpret_cast<const float4*>(g_tab + idx * 100);
    const float4* r1 = reinterpret_cast<const float4*>(g_tab + (idx + 1) * 100);
    __syncthreads();

#pragma unroll 1
    for (int chunk = 0; chunk < 5; chunk++) {
#pragma unroll
        for (int q = 0; q < 5; q++) {
            float4 a = __ldg(&r0[chunk * 5 + q]);
            float4 b = __ldg(&r1[chunk * 5 + q]);
            sG[tid * 21 + q * 4 + 0] = fmaf(frac, b.x - a.x, a.x);
            sG[tid * 21 + q * 4 + 1] = fmaf(frac, b.y - a.y, a.y);
            sG[tid * 21 + q * 4 + 2] = fmaf(frac, b.z - a.z, a.z);
            sG[tid * 21 + q * 4 + 3] = fmaf(frac, b.w - a.w, a.w);
        }
        __syncthreads();
        if (tid < 80) {
            int f = tid / 20, c = tid - f * 20;
            float a0 = 0.0f, a1 = 0.0f, a2 = 0.0f, a3 = 0.0f;
#pragma unroll 8
            for (int j = 0; j < 128; j += 4) {
                a0 = fmaf(sRi[((j + 0) << 2) + f], sG[(j + 0) * 21 + c], a0);
                a1 = fmaf(sRi[((j + 1) << 2) + f], sG[(j + 1) * 21 + c], a1);
                a2 = fmaf(sRi[((j + 2) << 2) + f], sG[(j + 2) * 21 + c], a2);
                a3 = fmaf(sRi[((j + 3) << 2) + f], sG[(j + 3) * 21 + c], a3);
            }
            sB[f * 100 + chunk * 20 + c] = (a0 + a1) + (a2 + a3);
        }
        __syncthreads();
    }

    for (int o = tid; o < 400; o += 128)
        g_B[atom * 400 + o] = sB[o];
}

// ---------------- Etot ----------------
__global__ __launch_bounds__(128) void etot_kernel(float* __restrict__ out)
{
    __shared__ float red[4];
    int b = blockIdx.x;
    int tid = threadIdx.x;
    float a = 0.0f;
    for (int i = tid; i < N_; i += 128) a += out[8 + b * N_ + i];
#pragma unroll
    for (int off = 16; off; off >>= 1) a += __shfl_xor_sync(0xFFFFFFFFu, a, off);
    if ((tid & 31) == 0) red[tid >> 5] = a;
    __syncthreads();
    if (tid == 0) out[b] = red[0] + red[1] + red[2] + red[3];
}

// ---------------- launch ----------------
extern "C" void kernel_launch(void* const* d_in, const int* in_sizes, int n_in,
                              void* d_out, int out_size)
{
    const float* img = (const float*)d_in[0];
    const float* ew0 = (const float*)d_in[1];
    const float* eb0 = (const float*)d_in[2];
    const float* ew1 = (const float*)d_in[3];
    const float* eb1 = (const float*)d_in[4];
    const float* ew2 = (const float*)d_in[5];
    const float* eb2 = (const float*)d_in[6];
    const float* fw0 = (const float*)d_in[7];
    const float* fb0 = (const float*)d_in[8];
    const float* fw1 = (const float*)d_in[9];
    const float* fb1 = (const float*)d_in[10];
    const float* fw2 = (const float*)d_in[11];
    const float* fb2 = (const float*)d_in[12];
    const float* fw3 = (const float*)d_in[13];
    const float* fb3 = (const float*)d_in[14];
    float* out = (float*)d_out;

    void *pB, *pH1, *pH2, *pWT1, *pWT2, *pWT3;
    cudaGetSymbolAddress(&pB,  g_B);
    cudaGetSymbolAddress(&pH1, g_H1);
    cudaGetSymbolAddress(&pH2, g_H2);
    cudaGetSymbolAddress(&pWT1, g_WT1);
    cudaGetSymbolAddress(&pWT2, g_WT2);
    cudaGetSymbolAddress(&pWT3, g_WT3);

    cudaFuncSetAttribute(mma_gemm<true, false>,
                         cudaFuncAttributeMaxDynamicSharedMemorySize, SMB_G1);
    cudaFuncSetAttribute(mma_gemm<false, false>,
                         cudaFuncAttributeMaxDynamicSharedMemorySize, SMB_G23);
    cudaFuncSetAttribute(mma_gemm<false, true>,
                         cudaFuncAttributeMaxDynamicSharedMemorySize, SMB_G23);

    transpose_all_kernel<<<dim3(50, 8, 3), dim3(32, 8)>>>(
        fw0, fw1, fw2, (float*)pWT1, (float*)pWT2, (float*)pWT3);
    build_tab_kernel<<<33, 128>>>(ew0, eb0, ew1, eb1, ew2, eb2);
    embed_kernel<<<ATOMS, 128>>>((const float4*)img);

    // launch index 3 (profiled slot): fused GEMM1
    mma_gemm<true, false><<<ATOMS / 32, NT, SMB_G1>>>(
        (const float*)pB, (const float*)pWT1, fb0, (float*)pH1, DRDIM,
        nullptr, nullptr, nullptr);
    mma_gemm<false, false><<<ATOMS / 32, NT, SMB_G23>>>(
        (const float*)pH1, (const float*)pWT2, fb1, (float*)pH2, F0,
        nullptr, nullptr, nullptr);
    mma_gemm<false, true><<<ATOMS / 32, NT, SMB_G23>>>(
        (const float*)pH2, (const float*)pWT3, fb2, nullptr, F0,
        fw3, fb3, out);

    etot_kernel<<<B_, 128>>>(out);
}

// round 15
// speedup vs baseline: 1.3102x; 1.2712x over previous
#include <cuda_runtime.h>
#include <cuda_bf16.h>
#include <math.h>
#include <cstdint>

#define B_    8
#define N_    512
#define KN    128
#define ATOMS 4096
#define DRDIM 1600
#define F0    240
#define NTAB  512
#define SMAXF 1.3335f

// ---------------- scratch ----------------
__device__ float g_B [ATOMS * 400];   // tmpB [atom][f*100+h]
__device__ float g_H1[ATOMS * F0];
__device__ float g_H2[ATOMS * F0];
__device__ float g_tab[(NTAB + 1) * 100];
__device__ __nv_bfloat16 g_W1h[F0 * DRDIM];  // fw0^T split: [240][1600]
__device__ __nv_bfloat16 g_W1l[F0 * DRDIM];
__device__ __nv_bfloat16 g_W2h[F0 * F0];
__device__ __nv_bfloat16 g_W2l[F0 * F0];
__device__ __nv_bfloat16 g_W3h[F0 * F0];
__device__ __nv_bfloat16 g_W3l[F0 * F0];

__device__ __forceinline__ float tanhfast(float x) {
    float e = __expf(2.0f * x);
    return 1.0f - __fdividef(2.0f, e + 1.0f);
}

__device__ __forceinline__ uint32_t bf16x2_split_hi(float v0, float v1,
                                                    float& r0, float& r1) {
    __nv_bfloat16 h0 = __float2bfloat16_rn(v0);
    __nv_bfloat16 h1 = __float2bfloat16_rn(v1);
    r0 = v0 - __bfloat162float(h0);
    r1 = v1 - __bfloat162float(h1);
    return (uint32_t)__bfloat16_as_ushort(h0)
         | ((uint32_t)__bfloat16_as_ushort(h1) << 16);
}
__device__ __forceinline__ uint32_t bf16x2_pack(float v0, float v1) {
    return (uint32_t)__bfloat16_as_ushort(__float2bfloat16_rn(v0))
         | ((uint32_t)__bfloat16_as_ushort(__float2bfloat16_rn(v1)) << 16);
}

// m16n8k16 bf16 mma: D += A*B
__device__ __forceinline__ void mma16(float* d, const uint32_t* a,
                                      uint32_t b0, uint32_t b1) {
    asm volatile(
        "mma.sync.aligned.m16n8k16.row.col.f32.bf16.bf16.f32 "
        "{%0,%1,%2,%3}, {%4,%5,%6,%7}, {%8,%9}, {%0,%1,%2,%3};"
        : "+f"(d[0]), "+f"(d[1]), "+f"(d[2]), "+f"(d[3])
        : "r"(a[0]), "r"(a[1]), "r"(a[2]), "r"(a[3]), "r"(b0), "r"(b1));
}

#define NT 384
#define TBS 404

// ====== bf16 3-term mma GEMM: C[4096,240] = tanh(A @ W^T + bias) ======
// 384 threads = 12 warps: wm in {0,1} (16 rows), wn in {0..5} (40 cols, 5 frags).
// BM=32. Weights pre-split into bf16 hi/lo [N][K] in global.
// FUSED: A synthesized per-tile from tmpB (rank-4 DR). FUSE_EI: emits Ei.
template<int BK, bool FUSED, bool FUSE_EI>
__global__ __launch_bounds__(NT) void mma_gemm(
    const float* __restrict__ A,
    const __nv_bfloat16* __restrict__ Wh, const __nv_bfloat16* __restrict__ Wl,
    const float* __restrict__ bias, float* __restrict__ C, int K,
    const float* __restrict__ fw3, const float* __restrict__ fb3,
    float* __restrict__ out)
{
    constexpr int PW  = BK / 2 + 4;          // padded row stride in words
    constexpr int WA  = 32 * PW;             // A region words per (buf,mat)
    constexpr int WB  = 240 * PW;            // B region words per (buf,mat)
    constexpr int WOBb = 4 * WA;
    constexpr int WBIAS = 4 * WA + 4 * WB;
    constexpr int WFW3  = WBIAS + 240;
    constexpr int WTB   = WBIAS + 480;       // tmpB fp32 region (FUSED)
    constexpr int WEI   = 4 * WA;            // EI tile region (reuses B)
    constexpr int SES   = 242;
    constexpr int BCH = 240 * (BK / 8);      // uint4 per B matrix per tile
    constexpr int NB  = (2 * BCH + NT - 1) / NT;
    constexpr int NA  = (8 * BK + NT - 1) / NT;

    extern __shared__ uint32_t smw[];
    float* smf = (float*)smw;

    const int tid  = threadIdx.x;
    const int lane = tid & 31;
    const int wid  = tid >> 5;        // 0..11
    const int wm   = wid & 1;
    const int wn   = wid >> 1;        // 0..5
    const int gid  = lane >> 2;
    const int tig  = lane & 3;
    const int bm   = blockIdx.x * 32;
    const int T    = K / BK;

    for (int i = tid; i < F0; i += NT) smf[WBIAS + i] = bias[i];
    if (FUSE_EI)
        for (int i = tid; i < F0; i += NT) smf[WFW3 + i] = fw3[i];
    if (FUSED) {
        for (int i = tid; i < 3200; i += NT) {
            int at = i / 100, q = i - at * 100;
            float4 v = *(const float4*)(A + (size_t)(bm + at) * 400 + q * 4);
            *(float4*)(smf + WTB + at * TBS + q * 4) = v;
        }
    }

    float acc[5][4];
#pragma unroll
    for (int f = 0; f < 5; f++)
#pragma unroll
        for (int j = 0; j < 4; j++) acc[f][j] = 0.0f;

    float4 avv[NA];
    uint4  bvv[NB];

    auto ldg_tile = [&](int kk0) {
        if (!FUSED) {
#pragma unroll
            for (int j = 0; j < NA; j++) {
                int i = tid + j * NT;
                if (i < 8 * BK) {
                    int row = i / (BK / 4), c4 = i % (BK / 4);
                    avv[j] = *(const float4*)(A + (size_t)(bm + row) * K + kk0 + c4 * 4);
                }
            }
        }
#pragma unroll
        for (int j = 0; j < NB; j++) {
            int i = tid + j * NT;
            if (i < 2 * BCH) {
                int mat = i / BCH;
                int rem = i - mat * BCH;
                int r = rem / (BK / 8), h = rem % (BK / 8);
                const __nv_bfloat16* W = mat ? Wl : Wh;
                bvv[j] = *(const uint4*)(W + (size_t)r * K + kk0 + h * 8);
            }
        }
    };

    auto sts_tile = [&](int buf, int kk0) {
#pragma unroll
        for (int j = 0; j < NB; j++) {
            int i = tid + j * NT;
            if (i < 2 * BCH) {
                int mat = i / BCH;
                int rem = i - mat * BCH;
                int r = rem / (BK / 8), h = rem % (BK / 8);
                *(uint4*)(smw + WOBb + (buf * 2 + mat) * WB + r * PW + h * 4) = bvv[j];
            }
        }
        if (FUSED) {
            for (int i = tid; i < 16 * BK; i += NT) {
                int row = i / (BK / 2), kw = i % (BK / 2);
                const float* rp = smf + WTB + row * TBS;
                float v[2];
#pragma unroll
                for (int j = 0; j < 2; j++) {
                    int c = kk0 + kw * 2 + j;
                    int m = c / 100, hh = c - m * 100;
                    v[j] = rp[m]       * rp[hh]
                         + rp[100 + m] * rp[100 + hh]
                         + rp[200 + m] * rp[200 + hh]
                         + rp[300 + m] * rp[300 + hh];
                }
                float r0, r1;
                uint32_t hw = bf16x2_split_hi(v[0], v[1], r0, r1);
                uint32_t lw = bf16x2_pack(r0, r1);
                smw[(buf * 2 + 0) * WA + row * PW + kw] = hw;
                smw[(buf * 2 + 1) * WA + row * PW + kw] = lw;
            }
        } else {
#pragma unroll
            for (int j = 0; j < NA; j++) {
                int i = tid + j * NT;
                if (i < 8 * BK) {
                    int row = i / (BK / 4), c4 = i % (BK / 4);
                    float4 vv = avv[j];
                    float r0, r1, r2, r3;
                    uint32_t h0 = bf16x2_split_hi(vv.x, vv.y, r0, r1);
                    uint32_t h1 = bf16x2_split_hi(vv.z, vv.w, r2, r3);
                    uint32_t l0 = bf16x2_pack(r0, r1);
                    uint32_t l1 = bf16x2_pack(r2, r3);
                    int wbase = row * PW + c4 * 2;
                    smw[(buf * 2 + 0) * WA + wbase]     = h0;
                    smw[(buf * 2 + 0) * WA + wbase + 1] = h1;
                    smw[(buf * 2 + 1) * WA + wbase]     = l0;
                    smw[(buf * 2 + 1) * WA + wbase + 1] = l1;
                }
            }
        }
    };

    ldg_tile(0);
    if (FUSED) __syncthreads();   // tmpB staged before A synthesis
    sts_tile(0, 0);
    __syncthreads();

    for (int t = 0; t < T; t++) {
        const int buf = t & 1;
        if (t + 1 < T) ldg_tile((t + 1) * BK);

        const uint32_t* pAh = smw + (buf * 2 + 0) * WA;
        const uint32_t* pAl = smw + (buf * 2 + 1) * WA;
        const uint32_t* pBh = smw + WOBb + (buf * 2 + 0) * WB;
        const uint32_t* pBl = smw + WOBb + (buf * 2 + 1) * WB;
        const int ra = wm * 16 + gid;
#pragma unroll
        for (int ks = 0; ks < BK / 16; ks++) {
            const int k0 = ks * 8;
            uint32_t ah[4], al[4];
            ah[0] = pAh[ ra      * PW + k0 + tig];
            ah[1] = pAh[(ra + 8) * PW + k0 + tig];
            ah[2] = pAh[ ra      * PW + k0 + tig + 4];
            ah[3] = pAh[(ra + 8) * PW + k0 + tig + 4];
            al[0] = pAl[ ra      * PW + k0 + tig];
            al[1] = pAl[(ra + 8) * PW + k0 + tig];
            al[2] = pAl[ ra      * PW + k0 + tig + 4];
            al[3] = pAl[(ra + 8) * PW + k0 + tig + 4];
#pragma unroll
            for (int nf = 0; nf < 5; nf++) {
                const int rb = wn * 40 + nf * 8 + gid;
                uint32_t bh0 = pBh[rb * PW + k0 + tig];
                uint32_t bh1 = pBh[rb * PW + k0 + tig + 4];
                uint32_t bl0 = pBl[rb * PW + k0 + tig];
                uint32_t bl1 = pBl[rb * PW + k0 + tig + 4];
                mma16(acc[nf], ah, bh0, bh1);
                mma16(acc[nf], ah, bl0, bl1);
                mma16(acc[nf], al, bh0, bh1);
            }
        }
        if (t + 1 < T) sts_tile(1 - buf, (t + 1) * BK);
        __syncthreads();
    }

    // epilogue: bias + tanh
    const int lr0 = wm * 16 + gid;
#pragma unroll
    for (int nf = 0; nf < 5; nf++) {
        const int col = wn * 40 + nf * 8 + tig * 2;
        const float b0 = smf[WBIAS + col];
        const float b1 = smf[WBIAS + col + 1];
        float2 v0, v1;
        v0.x = tanhfast(acc[nf][0] + b0);
        v0.y = tanhfast(acc[nf][1] + b1);
        v1.x = tanhfast(acc[nf][2] + b0);
        v1.y = tanhfast(acc[nf][3] + b1);
        if (FUSE_EI) {
            *(float2*)(smf + WEI + lr0 * SES + col)       = v0;
            *(float2*)(smf + WEI + (lr0 + 8) * SES + col) = v1;
        } else {
            *(float2*)(C + (size_t)(bm + lr0) * F0 + col)     = v0;
            *(float2*)(C + (size_t)(bm + lr0 + 8) * F0 + col) = v1;
        }
    }

    if (FUSE_EI) {
        __syncthreads();
        const float fb3v = __ldg(fb3);
        for (int r = wid; r < 32; r += 12) {
            const float* row = smf + WEI + r * SES;
            float a = 0.0f;
#pragma unroll
            for (int i = lane; i < F0; i += 32)
                a = fmaf(row[i], smf[WFW3 + i], a);
#pragma unroll
            for (int off = 16; off; off >>= 1)
                a += __shfl_xor_sync(0xFFFFFFFFu, a, off);
            if (lane == 0) out[8 + bm + r] = a + fb3v;
        }
    }
}

// ------- transpose + bf16 hi/lo split: W[K][N] -> Wh/Wl [N][K] -------
__global__ __launch_bounds__(256) void transpose_all_kernel(
    const float* __restrict__ fw0, const float* __restrict__ fw1,
    const float* __restrict__ fw2,
    __nv_bfloat16* __restrict__ w1h, __nv_bfloat16* __restrict__ w1l,
    __nv_bfloat16* __restrict__ w2h, __nv_bfloat16* __restrict__ w2l,
    __nv_bfloat16* __restrict__ w3h, __nv_bfloat16* __restrict__ w3l)
{
    __shared__ float t[32][33];
    const int z = blockIdx.z;
    const float* W = (z == 0) ? fw0 : (z == 1) ? fw1 : fw2;
    __nv_bfloat16* Wh = (z == 0) ? w1h : (z == 1) ? w2h : w3h;
    __nv_bfloat16* Wl = (z == 0) ? w1l : (z == 1) ? w2l : w3l;
    const int K = (z == 0) ? DRDIM : F0;
    const int N = F0;
    int k0 = blockIdx.x * 32, n0 = blockIdx.y * 32;
    if (k0 >= K) return;
    int x = threadIdx.x, y = threadIdx.y;
#pragma unroll
    for (int dy = 0; dy < 32; dy += 8) {
        int k = k0 + y + dy, n = n0 + x;
        t[y + dy][x] = (k < K && n < N) ? W[(size_t)k * N + n] : 0.0f;
    }
    __syncthreads();
#pragma unroll
    for (int dy = 0; dy < 32; dy += 8) {
        int n = n0 + y + dy, k = k0 + x;
        if (n < N && k < K) {
            float v = t[x][y + dy];
            __nv_bfloat16 h = __float2bfloat16_rn(v);
            Wh[(size_t)n * K + k] = h;
            Wl[(size_t)n * K + k] = __float2bfloat16_rn(v - __bfloat162float(h));
        }
    }
}

// ---------------- build G(S) table: 16 nodes per block ----------------
__global__ __launch_bounds__(128) void build_tab_kernel(
    const float* __restrict__ ew0, const float* __restrict__ eb0,
    const float* __restrict__ ew1, const float* __restrict__ eb1,
    const float* __restrict__ ew2, const float* __restrict__ eb2)
{
    __shared__ float sw1[25 * 50];
    __shared__ float sw2[50 * 100];
    __shared__ float sh1[25], sh2[50];

    const int tid = threadIdx.x;
    for (int k = tid; k < 1250; k += 128) sw1[k] = ew1[k];
    for (int k = tid; k < 5000; k += 128) sw2[k] = ew2[k];
    __syncthreads();

    for (int n = 0; n < 16; n++) {
        const int i = blockIdx.x * 16 + n;
        if (i > NTAB) break;
        const float S = (float)i * (SMAXF / (float)NTAB);
        if (tid < 25)
            sh1[tid] = tanhfast(fmaf(S, __ldg(&ew0[tid]), __ldg(&eb0[tid])));
        __syncthreads();
        if (tid < 50) {
            float a = __ldg(&eb1[tid]);
#pragma unroll
            for (int q = 0; q < 25; q++) a = fmaf(sh1[q], sw1[q * 50 + tid], a);
            sh2[tid] = tanhfast(a);
        }
        __syncthreads();
        if (tid < 100) {
            float g = __ldg(&eb2[tid]);
#pragma unroll
            for (int q = 0; q < 50; q++) g = fmaf(sh2[q], sw2[q * 100 + tid], g);
            g_tab[i * 100 + tid] = tanhfast(g);
        }
        __syncthreads();
    }
}

// ---------------- embed: geometry + table interp -> tmpB ----------------
__global__ __launch_bounds__(128) void embed_kernel(const float4* __restrict__ img)
{
    __shared__ float sRi[128 * 4];
    __shared__ float sG[128 * 21];
    __shared__ float sB[400];

    const int tid = threadIdx.x;
    const int atom = blockIdx.x;

    float4 p = img[atom * KN + tid];
    float R = p.x * p.x + p.y * p.y + p.z * p.z;
    bool mask = p.w > 0.0f;
    float S = 0.0f;
    if (R < 10.0f) {
        if (mask) S = 1.0f / R;
    } else if (R < 25.0f) {
        S = 0.5f * cosf(0.20943951023931953f * (R - 10.0f)) + 0.5f;
    }
    float coef = mask ? S / R : 0.0f;
    sRi[tid * 4 + 0] = S;
    sRi[tid * 4 + 1] = coef * p.x;
    sRi[tid * 4 + 2] = coef * p.y;
    sRi[tid * 4 + 3] = coef * p.z;

    float t = S * ((float)NTAB / SMAXF);
    int idx = (int)t;
    if (idx > NTAB - 1) idx = NTAB - 1;
    float frac = t - (float)idx;
    const float4* r0 = reinterpret_cast<const float4*>(g_tab + idx * 100);
    const float4* r1 = reinterpret_cast<const float4*>(g_tab + (idx + 1) * 100);
    __syncthreads();

#pragma unroll 1
    for (int chunk = 0; chunk < 5; chunk++) {
#pragma unroll
        for (int q = 0; q < 5; q++) {
            float4 a = __ldg(&r0[chunk * 5 + q]);
            float4 b = __ldg(&r1[chunk * 5 + q]);
            sG[tid * 21 + q * 4 + 0] = fmaf(frac, b.x - a.x, a.x);
            sG[tid * 21 + q * 4 + 1] = fmaf(frac, b.y - a.y, a.y);
            sG[tid * 21 + q * 4 + 2] = fmaf(frac, b.z - a.z, a.z);
            sG[tid * 21 + q * 4 + 3] = fmaf(frac, b.w - a.w, a.w);
        }
        __syncthreads();
        if (tid < 80) {
            int f = tid / 20, c = tid - f * 20;
            float a0 = 0.0f, a1 = 0.0f, a2 = 0.0f, a3 = 0.0f;
#pragma unroll 8
            for (int j = 0; j < 128; j += 4) {
                a0 = fmaf(sRi[((j + 0) << 2) + f], sG[(j + 0) * 21 + c], a0);
                a1 = fmaf(sRi[((j + 1) << 2) + f], sG[(j + 1) * 21 + c], a1);
                a2 = fmaf(sRi[((j + 2) << 2) + f], sG[(j + 2) * 21 + c], a2);
                a3 = fmaf(sRi[((j + 3) << 2) + f], sG[(j + 3) * 21 + c], a3);
            }
            sB[f * 100 + chunk * 20 + c] = (a0 + a1) + (a2 + a3);
        }
        __syncthreads();
    }

    for (int o = tid; o < 400; o += 128)
        g_B[atom * 400 + o] = sB[o];
}

// ---------------- Etot ----------------
__global__ __launch_bounds__(128) void etot_kernel(float* __restrict__ out)
{
    __shared__ float red[4];
    int b = blockIdx.x;
    int tid = threadIdx.x;
    float a = 0.0f;
    for (int i = tid; i < N_; i += 128) a += out[8 + b * N_ + i];
#pragma unroll
    for (int off = 16; off; off >>= 1) a += __shfl_xor_sync(0xFFFFFFFFu, a, off);
    if ((tid & 31) == 0) red[tid >> 5] = a;
    __syncthreads();
    if (tid == 0) out[b] = red[0] + red[1] + red[2] + red[3];
}

// ---------------- launch ----------------
extern "C" void kernel_launch(void* const* d_in, const int* in_sizes, int n_in,
                              void* d_out, int out_size)
{
    const float* img = (const float*)d_in[0];
    const float* ew0 = (const float*)d_in[1];
    const float* eb0 = (const float*)d_in[2];
    const float* ew1 = (const float*)d_in[3];
    const float* eb1 = (const float*)d_in[4];
    const float* ew2 = (const float*)d_in[5];
    const float* eb2 = (const float*)d_in[6];
    const float* fw0 = (const float*)d_in[7];
    const float* fb0 = (const float*)d_in[8];
    const float* fw1 = (const float*)d_in[9];
    const float* fb1 = (const float*)d_in[10];
    const float* fw2 = (const float*)d_in[11];
    const float* fb2 = (const float*)d_in[12];
    const float* fw3 = (const float*)d_in[13];
    const float* fb3 = (const float*)d_in[14];
    float* out = (float*)d_out;

    void *pB, *pH1, *pH2;
    void *pW1h, *pW1l, *pW2h, *pW2l, *pW3h, *pW3l;
    cudaGetSymbolAddress(&pB,  g_B);
    cudaGetSymbolAddress(&pH1, g_H1);
    cudaGetSymbolAddress(&pH2, g_H2);
    cudaGetSymbolAddress(&pW1h, g_W1h);
    cudaGetSymbolAddress(&pW1l, g_W1l);
    cudaGetSymbolAddress(&pW2h, g_W2h);
    cudaGetSymbolAddress(&pW2l, g_W2l);
    cudaGetSymbolAddress(&pW3h, g_W3h);
    cudaGetSymbolAddress(&pW3l, g_W3l);

    // smem: BK=32 -> 35168 words; BK=48 -> 30944 words
    const int SMB_G1  = 35168 * 4;
    const int SMB_G23 = 30944 * 4;
    cudaFuncSetAttribute(mma_gemm<32, true, false>,
                         cudaFuncAttributeMaxDynamicSharedMemorySize, SMB_G1);
    cudaFuncSetAttribute(mma_gemm<48, false, false>,
                         cudaFuncAttributeMaxDynamicSharedMemorySize, SMB_G23);
    cudaFuncSetAttribute(mma_gemm<48, false, true>,
                         cudaFuncAttributeMaxDynamicSharedMemorySize, SMB_G23);

    transpose_all_kernel<<<dim3(50, 8, 3), dim3(32, 8)>>>(
        fw0, fw1, fw2,
        (__nv_bfloat16*)pW1h, (__nv_bfloat16*)pW1l,
        (__nv_bfloat16*)pW2h, (__nv_bfloat16*)pW2l,
        (__nv_bfloat16*)pW3h, (__nv_bfloat16*)pW3l);
    build_tab_kernel<<<33, 128>>>(ew0, eb0, ew1, eb1, ew2, eb2);
    embed_kernel<<<ATOMS, 128>>>((const float4*)img);

    // launch index 3 (profiled slot): fused GEMM1, K=1600, BK=32
    mma_gemm<32, true, false><<<ATOMS / 32, NT, SMB_G1>>>(
        (const float*)pB, (const __nv_bfloat16*)pW1h, (const __nv_bfloat16*)pW1l,
        fb0, (float*)pH1, DRDIM, nullptr, nullptr, nullptr);
    mma_gemm<48, false, false><<<ATOMS / 32, NT, SMB_G23>>>(
        (const float*)pH1, (const __nv_bfloat16*)pW2h, (const __nv_bfloat16*)pW2l,
        fb1, (float*)pH2, F0, nullptr, nullptr, nullptr);
    mma_gemm<48, false, true><<<ATOMS / 32, NT, SMB_G23>>>(
        (const float*)pH2, (const __nv_bfloat16*)pW3h, (const __nv_bfloat16*)pW3l,
        fb2, nullptr, F0, fw3, fb3, out);

    etot_kernel<<<B_, 128>>>(out);
}

// round 17
// speedup vs baseline: 1.4187x; 1.0829x over previous
#include <cuda_runtime.h>
#include <cuda_bf16.h>
#include <math.h>
#include <cstdint>

#define B_    8
#define N_    512
#define KN    128
#define ATOMS 4096
#define DRDIM 1600
#define F0    240
#define NTAB  512
#define SMAXF 1.3335f

// ---------------- scratch ----------------
__device__ float g_B [ATOMS * 400];   // tmpB [atom][f*100+h]
__device__ float g_H1[ATOMS * F0];
__device__ float g_H2[ATOMS * F0];
__device__ float g_tab[(NTAB + 1) * 100];
__device__ __nv_bfloat16 g_W1h[F0 * DRDIM];  // fw0^T split: [240][1600]
__device__ __nv_bfloat16 g_W1l[F0 * DRDIM];
__device__ __nv_bfloat16 g_W2h[F0 * F0];
__device__ __nv_bfloat16 g_W2l[F0 * F0];
__device__ __nv_bfloat16 g_W3h[F0 * F0];
__device__ __nv_bfloat16 g_W3l[F0 * F0];

__device__ __forceinline__ float tanhfast(float x) {
    float e = __expf(2.0f * x);
    return 1.0f - __fdividef(2.0f, e + 1.0f);
}

__device__ __forceinline__ uint32_t bf16x2_split_hi(float v0, float v1,
                                                    float& r0, float& r1) {
    __nv_bfloat16 h0 = __float2bfloat16_rn(v0);
    __nv_bfloat16 h1 = __float2bfloat16_rn(v1);
    r0 = v0 - __bfloat162float(h0);
    r1 = v1 - __bfloat162float(h1);
    return (uint32_t)__bfloat16_as_ushort(h0)
         | ((uint32_t)__bfloat16_as_ushort(h1) << 16);
}
__device__ __forceinline__ uint32_t bf16x2_pack(float v0, float v1) {
    return (uint32_t)__bfloat16_as_ushort(__float2bfloat16_rn(v0))
         | ((uint32_t)__bfloat16_as_ushort(__float2bfloat16_rn(v1)) << 16);
}

// m16n8k16 bf16 mma: D += A*B
__device__ __forceinline__ void mma16(float* d, const uint32_t* a,
                                      uint32_t b0, uint32_t b1) {
    asm volatile(
        "mma.sync.aligned.m16n8k16.row.col.f32.bf16.bf16.f32 "
        "{%0,%1,%2,%3}, {%4,%5,%6,%7}, {%8,%9}, {%0,%1,%2,%3};"
        : "+f"(d[0]), "+f"(d[1]), "+f"(d[2]), "+f"(d[3])
        : "r"(a[0]), "r"(a[1]), "r"(a[2]), "r"(a[3]), "r"(b0), "r"(b1));
}

__device__ __forceinline__ void ldsm4(uint32_t* r, uint32_t addr) {
    asm volatile("ldmatrix.sync.aligned.m8n8.x4.shared.b16 {%0,%1,%2,%3}, [%4];"
        : "=r"(r[0]), "=r"(r[1]), "=r"(r[2]), "=r"(r[3]) : "r"(addr));
}
__device__ __forceinline__ void ldsm2(uint32_t* r, uint32_t addr) {
    asm volatile("ldmatrix.sync.aligned.m8n8.x2.shared.b16 {%0,%1}, [%2];"
        : "=r"(r[0]), "=r"(r[1]) : "r"(addr));
}

#define NT 384
#define TBS 404

// ====== bf16 3-term mma GEMM: C[4096,240] = tanh(A @ W^T + bias) ======
// 384 threads = 12 warps: wm in {0,1} (16 rows), wn in {0..5} (40 cols, 5 frags).
// Fragment loads via ldmatrix (canonical layout). Weights pre-split bf16 hi/lo.
template<int BK, bool FUSED, bool FUSE_EI>
__global__ __launch_bounds__(NT) void mma_gemm(
    const float* __restrict__ A,
    const __nv_bfloat16* __restrict__ Wh, const __nv_bfloat16* __restrict__ Wl,
    const float* __restrict__ bias, float* __restrict__ C, int K,
    const float* __restrict__ fw3, const float* __restrict__ fb3,
    float* __restrict__ out)
{
    constexpr int PW  = BK / 2 + 4;          // padded row stride in words
    constexpr int WA  = 32 * PW;
    constexpr int WB  = 240 * PW;
    constexpr int WOBb = 4 * WA;
    constexpr int WBIAS = 4 * WA + 4 * WB;
    constexpr int WFW3  = WBIAS + 240;
    constexpr int WTB   = WBIAS + 480;
    constexpr int WEI   = 4 * WA;
    constexpr int SES   = 242;
    constexpr int BCH = 240 * (BK / 8);
    constexpr int NB  = (2 * BCH + NT - 1) / NT;
    constexpr int NA  = (8 * BK + NT - 1) / NT;

    extern __shared__ uint32_t smw[];
    float* smf = (float*)smw;
    const uint32_t smb = (uint32_t)__cvta_generic_to_shared(smw);

    const int tid  = threadIdx.x;
    const int lane = tid & 31;
    const int wid  = tid >> 5;
    const int wm   = wid & 1;
    const int wn   = wid >> 1;        // 0..5
    const int gid  = lane >> 2;
    const int tig  = lane & 3;
    const int bm   = blockIdx.x * 32;
    const int T    = K / BK;

    // ldmatrix per-lane byte offsets (within a (buf,mat) region)
    const uint32_t offA  = (uint32_t)(((wm * 16 + (lane & 15)) * PW + (lane >> 4) * 4) * 4);
    const uint32_t offBg = (uint32_t)((((lane >> 4) * 8 + (lane & 7)) * PW + ((lane >> 3) & 1) * 4) * 4);
    const uint32_t offB2 = (uint32_t)(((wn * 40 + 32 + (lane & 7)) * PW + ((lane >> 3) & 1) * 4) * 4);
    const uint32_t bg0 = (uint32_t)((wn * 40) * PW * 4);
    const uint32_t bg1 = (uint32_t)((wn * 40 + 16) * PW * 4);

    for (int i = tid; i < F0; i += NT) smf[WBIAS + i] = bias[i];
    if (FUSE_EI)
        for (int i = tid; i < F0; i += NT) smf[WFW3 + i] = fw3[i];
    if (FUSED) {
        for (int i = tid; i < 3200; i += NT) {
            int at = i / 100, q = i - at * 100;
            float4 v = *(const float4*)(A + (size_t)(bm + at) * 400 + q * 4);
            *(float4*)(smf + WTB + at * TBS + q * 4) = v;
        }
    }

    float acc[5][4];
#pragma unroll
    for (int f = 0; f < 5; f++)
#pragma unroll
        for (int j = 0; j < 4; j++) acc[f][j] = 0.0f;

    float4 avv[NA];
    uint4  bvv[NB];

    auto ldg_tile = [&](int kk0) {
        if (!FUSED) {
#pragma unroll
            for (int j = 0; j < NA; j++) {
                int i = tid + j * NT;
                if (i < 8 * BK) {
                    int row = i / (BK / 4), c4 = i % (BK / 4);
                    avv[j] = *(const float4*)(A + (size_t)(bm + row) * K + kk0 + c4 * 4);
                }
            }
        }
#pragma unroll
        for (int j = 0; j < NB; j++) {
            int i = tid + j * NT;
            if (i < 2 * BCH) {
                int mat = i / BCH;
                int rem = i - mat * BCH;
                int r = rem / (BK / 8), h = rem % (BK / 8);
                const __nv_bfloat16* W = mat ? Wl : Wh;
                bvv[j] = *(const uint4*)(W + (size_t)r * K + kk0 + h * 8);
            }
        }
    };

    auto sts_tile = [&](int buf, int kk0) {
#pragma unroll
        for (int j = 0; j < NB; j++) {
            int i = tid + j * NT;
            if (i < 2 * BCH) {
                int mat = i / BCH;
                int rem = i - mat * BCH;
                int r = rem / (BK / 8), h = rem % (BK / 8);
                *(uint4*)(smw + WOBb + (buf * 2 + mat) * WB + r * PW + h * 4) = bvv[j];
            }
        }
        if (FUSED) {
            for (int i = tid; i < 16 * BK; i += NT) {
                int row = i / (BK / 2), kw = i % (BK / 2);
                const float* rp = smf + WTB + row * TBS;
                float v[2];
#pragma unroll
                for (int j = 0; j < 2; j++) {
                    int c = kk0 + kw * 2 + j;
                    int m = c / 100, hh = c - m * 100;
                    v[j] = rp[m]       * rp[hh]
                         + rp[100 + m] * rp[100 + hh]
                         + rp[200 + m] * rp[200 + hh]
                         + rp[300 + m] * rp[300 + hh];
                }
                float r0, r1;
                uint32_t hw = bf16x2_split_hi(v[0], v[1], r0, r1);
                uint32_t lw = bf16x2_pack(r0, r1);
                smw[(buf * 2 + 0) * WA + row * PW + kw] = hw;
                smw[(buf * 2 + 1) * WA + row * PW + kw] = lw;
            }
        } else {
#pragma unroll
            for (int j = 0; j < NA; j++) {
                int i = tid + j * NT;
                if (i < 8 * BK) {
                    int row = i / (BK / 4), c4 = i % (BK / 4);
                    float4 vv = avv[j];
                    float r0, r1, r2, r3;
                    uint32_t h0 = bf16x2_split_hi(vv.x, vv.y, r0, r1);
                    uint32_t h1 = bf16x2_split_hi(vv.z, vv.w, r2, r3);
                    uint32_t l0 = bf16x2_pack(r0, r1);
                    uint32_t l1 = bf16x2_pack(r2, r3);
                    int wbase = row * PW + c4 * 2;
                    smw[(buf * 2 + 0) * WA + wbase]     = h0;
                    smw[(buf * 2 + 0) * WA + wbase + 1] = h1;
                    smw[(buf * 2 + 1) * WA + wbase]     = l0;
                    smw[(buf * 2 + 1) * WA + wbase + 1] = l1;
                }
            }
        }
    };

    ldg_tile(0);
    if (FUSED) __syncthreads();
    sts_tile(0, 0);
    __syncthreads();

    for (int t = 0; t < T; t++) {
        const int buf = t & 1;
        if (t + 1 < T) ldg_tile((t + 1) * BK);

        const uint32_t aHiB = smb + (uint32_t)((buf * 2 + 0) * WA * 4);
        const uint32_t aLoB = smb + (uint32_t)((buf * 2 + 1) * WA * 4);
        const uint32_t bHiB = smb + (uint32_t)((WOBb + (buf * 2 + 0) * WB) * 4);
        const uint32_t bLoB = smb + (uint32_t)((WOBb + (buf * 2 + 1) * WB) * 4);
#pragma unroll
        for (int ks = 0; ks < BK / 16; ks++) {
            const uint32_t kb = (uint32_t)(ks * 32);   // k0 bytes
            uint32_t ah[4], al[4];
            ldsm4(ah, aHiB + offA + kb);
            ldsm4(al, aLoB + offA + kb);
            uint32_t bh[10], bl[10];
            ldsm4(bh + 0, bHiB + bg0 + offBg + kb);
            ldsm4(bh + 4, bHiB + bg1 + offBg + kb);
            ldsm2(bh + 8, bHiB + offB2 + kb);
            ldsm4(bl + 0, bLoB + bg0 + offBg + kb);
            ldsm4(bl + 4, bLoB + bg1 + offBg + kb);
            ldsm2(bl + 8, bLoB + offB2 + kb);
#pragma unroll
            for (int nf = 0; nf < 5; nf++) {
                mma16(acc[nf], ah, bh[2 * nf], bh[2 * nf + 1]);
                mma16(acc[nf], ah, bl[2 * nf], bl[2 * nf + 1]);
                mma16(acc[nf], al, bh[2 * nf], bh[2 * nf + 1]);
            }
        }
        if (t + 1 < T) sts_tile(1 - buf, (t + 1) * BK);
        __syncthreads();
    }

    // epilogue: bias + tanh
    const int lr0 = wm * 16 + gid;
#pragma unroll
    for (int nf = 0; nf < 5; nf++) {
        const int col = wn * 40 + nf * 8 + tig * 2;
        const float b0 = smf[WBIAS + col];
        const float b1 = smf[WBIAS + col + 1];
        float2 v0, v1;
        v0.x = tanhfast(acc[nf][0] + b0);
        v0.y = tanhfast(acc[nf][1] + b1);
        v1.x = tanhfast(acc[nf][2] + b0);
        v1.y = tanhfast(acc[nf][3] + b1);
        if (FUSE_EI) {
            *(float2*)(smf + WEI + lr0 * SES + col)       = v0;
            *(float2*)(smf + WEI + (lr0 + 8) * SES + col) = v1;
        } else {
            *(float2*)(C + (size_t)(bm + lr0) * F0 + col)     = v0;
            *(float2*)(C + (size_t)(bm + lr0 + 8) * F0 + col) = v1;
        }
    }

    if (FUSE_EI) {
        __syncthreads();
        const float fb3v = __ldg(fb3);
        for (int r = wid; r < 32; r += 12) {
            const float* row = smf + WEI + r * SES;
            float a = 0.0f;
#pragma unroll
            for (int i = lane; i < F0; i += 32)
                a = fmaf(row[i], smf[WFW3 + i], a);
#pragma unroll
            for (int off = 16; off; off >>= 1)
                a += __shfl_xor_sync(0xFFFFFFFFu, a, off);
            if (lane == 0) out[8 + bm + r] = a + fb3v;
        }
    }
}

// ------- transpose + bf16 hi/lo split: W[K][N] -> Wh/Wl [N][K] -------
__global__ __launch_bounds__(256) void transpose_all_kernel(
    const float* __restrict__ fw0, const float* __restrict__ fw1,
    const float* __restrict__ fw2,
    __nv_bfloat16* __restrict__ w1h, __nv_bfloat16* __restrict__ w1l,
    __nv_bfloat16* __restrict__ w2h, __nv_bfloat16* __restrict__ w2l,
    __nv_bfloat16* __restrict__ w3h, __nv_bfloat16* __restrict__ w3l)
{
    __shared__ float t[32][33];
    const int z = blockIdx.z;
    const float* W = (z == 0) ? fw0 : (z == 1) ? fw1 : fw2;
    __nv_bfloat16* Wh = (z == 0) ? w1h : (z == 1) ? w2h : w3h;
    __nv_bfloat16* Wl = (z == 0) ? w1l : (z == 1) ? w2l : w3l;
    const int K = (z == 0) ? DRDIM : F0;
    const int N = F0;
    int k0 = blockIdx.x * 32, n0 = blockIdx.y * 32;
    if (k0 >= K) return;
    int x = threadIdx.x, y = threadIdx.y;
#pragma unroll
    for (int dy = 0; dy < 32; dy += 8) {
        int k = k0 + y + dy, n = n0 + x;
        t[y + dy][x] = (k < K && n < N) ? W[(size_t)k * N + n] : 0.0f;
    }
    __syncthreads();
#pragma unroll
    for (int dy = 0; dy < 32; dy += 8) {
        int n = n0 + y + dy, k = k0 + x;
        if (n < N && k < K) {
            float v = t[x][y + dy];
            __nv_bfloat16 h = __float2bfloat16_rn(v);
            Wh[(size_t)n * K + k] = h;
            Wl[(size_t)n * K + k] = __float2bfloat16_rn(v - __bfloat162float(h));
        }
    }
}

// ---------------- build G(S) table: 16 nodes per block ----------------
__global__ __launch_bounds__(128) void build_tab_kernel(
    const float* __restrict__ ew0, const float* __restrict__ eb0,
    const float* __restrict__ ew1, const float* __restrict__ eb1,
    const float* __restrict__ ew2, const float* __restrict__ eb2)
{
    __shared__ float sw1[25 * 50];
    __shared__ float sw2[50 * 100];
    __shared__ float sh1[25], sh2[50];

    const int tid = threadIdx.x;
    for (int k = tid; k < 1250; k += 128) sw1[k] = ew1[k];
    for (int k = tid; k < 5000; k += 128) sw2[k] = ew2[k];
    __syncthreads();

    for (int n = 0; n < 16; n++) {
        const int i = blockIdx.x * 16 + n;
        if (i > NTAB) break;
        const float S = (float)i * (SMAXF / (float)NTAB);
        if (tid < 25)
            sh1[tid] = tanhfast(fmaf(S, __ldg(&ew0[tid]), __ldg(&eb0[tid])));
        __syncthreads();
        if (tid < 50) {
            float a = __ldg(&eb1[tid]);
#pragma unroll
            for (int q = 0; q < 25; q++) a = fmaf(sh1[q], sw1[q * 50 + tid], a);
            sh2[tid] = tanhfast(a);
        }
        __syncthreads();
        if (tid < 100) {
            float g = __ldg(&eb2[tid]);
#pragma unroll
            for (int q = 0; q < 50; q++) g = fmaf(sh2[q], sw2[q * 100 + tid], g);
            g_tab[i * 100 + tid] = tanhfast(g);
        }
        __syncthreads();
    }
}

// ---------------- embed: geometry + table interp -> tmpB ----------------
// smem: sRi4 float4[128] (words 0..511), sG [128][100] (words 512..13311)
__global__ __launch_bounds__(128) void embed_kernel(const float4* __restrict__ img)
{
    extern __shared__ float es[];
    float4* sRi4 = (float4*)es;
    float* sG = es + 512;

    const int tid = threadIdx.x;
    const int atom = blockIdx.x;

    float4 p = img[atom * KN + tid];
    float R = p.x * p.x + p.y * p.y + p.z * p.z;
    bool mask = p.w > 0.0f;
    float S = 0.0f;
    if (R < 10.0f) {
        if (mask) S = 1.0f / R;
    } else if (R < 25.0f) {
        S = 0.5f * cosf(0.20943951023931953f * (R - 10.0f)) + 0.5f;
    }
    float coef = mask ? S / R : 0.0f;
    sRi4[tid] = make_float4(S, coef * p.x, coef * p.y, coef * p.z);

    float t = S * ((float)NTAB / SMAXF);
    int idx = (int)t;
    if (idx > NTAB - 1) idx = NTAB - 1;
    float frac = t - (float)idx;
    const float4* r0 = reinterpret_cast<const float4*>(g_tab + idx * 100);
    const float4* r1 = reinterpret_cast<const float4*>(g_tab + (idx + 1) * 100);

    // interp all 100 cols -> sG[tid][0..99] (stride 100, conflict-free f4 stores)
#pragma unroll
    for (int q = 0; q < 25; q++) {
        float4 a = __ldg(&r0[q]);
        float4 b = __ldg(&r1[q]);
        float4 g;
        g.x = fmaf(frac, b.x - a.x, a.x);
        g.y = fmaf(frac, b.y - a.y, a.y);
        g.z = fmaf(frac, b.z - a.z, a.z);
        g.w = fmaf(frac, b.w - a.w, a.w);
        *(float4*)(sG + tid * 100 + q * 4) = g;
    }
    __syncthreads();

    // tmpB[f][c] = sum_j Ri[j][f] * G[j][c]; thread c owns all 4 f's
    if (tid < 100) {
        float a0[4] = {0.f, 0.f, 0.f, 0.f};
        float a1[4] = {0.f, 0.f, 0.f, 0.f};
#pragma unroll 4
        for (int j = 0; j < 128; j += 2) {
            float4 r_0 = sRi4[j];
            float  g_0 = sG[j * 100 + tid];
            float4 r_1 = sRi4[j + 1];
            float  g_1 = sG[(j + 1) * 100 + tid];
            a0[0] = fmaf(r_0.x, g_0, a0[0]);
            a0[1] = fmaf(r_0.y, g_0, a0[1]);
            a0[2] = fmaf(r_0.z, g_0, a0[2]);
            a0[3] = fmaf(r_0.w, g_0, a0[3]);
            a1[0] = fmaf(r_1.x, g_1, a1[0]);
            a1[1] = fmaf(r_1.y, g_1, a1[1]);
            a1[2] = fmaf(r_1.z, g_1, a1[2]);
            a1[3] = fmaf(r_1.w, g_1, a1[3]);
        }
#pragma unroll
        for (int f = 0; f < 4; f++)
            g_B[atom * 400 + f * 100 + tid] = a0[f] + a1[f];
    }
}

// ---------------- Etot ----------------
__global__ __launch_bounds__(128) void etot_kernel(float* __restrict__ out)
{
    __shared__ float red[4];
    int b = blockIdx.x;
    int tid = threadIdx.x;
    float a = 0.0f;
    for (int i = tid; i < N_; i += 128) a += out[8 + b * N_ + i];
#pragma unroll
    for (int off = 16; off; off >>= 1) a += __shfl_xor_sync(0xFFFFFFFFu, a, off);
    if ((tid & 31) == 0) red[tid >> 5] = a;
    __syncthreads();
    if (tid == 0) out[b] = red[0] + red[1] + red[2] + red[3];
}

// ---------------- launch ----------------
extern "C" void kernel_launch(void* const* d_in, const int* in_sizes, int n_in,
                              void* d_out, int out_size)
{
    const float* img = (const float*)d_in[0];
    const float* ew0 = (const float*)d_in[1];
    const float* eb0 = (const float*)d_in[2];
    const float* ew1 = (const float*)d_in[3];
    const float* eb1 = (const float*)d_in[4];
    const float* ew2 = (const float*)d_in[5];
    const float* eb2 = (const float*)d_in[6];
    const float* fw0 = (const float*)d_in[7];
    const float* fb0 = (const float*)d_in[8];
    const float* fw1 = (const float*)d_in[9];
    const float* fb1 = (const float*)d_in[10];
    const float* fw2 = (const float*)d_in[11];
    const float* fb2 = (const float*)d_in[12];
    const float* fw3 = (const float*)d_in[13];
    const float* fb3 = (const float*)d_in[14];
    float* out = (float*)d_out;

    void *pB, *pH1, *pH2;
    void *pW1h, *pW1l, *pW2h, *pW2l, *pW3h, *pW3l;
    cudaGetSymbolAddress(&pB,  g_B);
    cudaGetSymbolAddress(&pH1, g_H1);
    cudaGetSymbolAddress(&pH2, g_H2);
    cudaGetSymbolAddress(&pW1h, g_W1h);
    cudaGetSymbolAddress(&pW1l, g_W1l);
    cudaGetSymbolAddress(&pW2h, g_W2h);
    cudaGetSymbolAddress(&pW2l, g_W2l);
    cudaGetSymbolAddress(&pW3h, g_W3h);
    cudaGetSymbolAddress(&pW3l, g_W3l);

    const int SMB_G1  = 35168 * 4;   // BK=32
    const int SMB_G23 = 30944 * 4;   // BK=48
    const int SMB_EMB = 13312 * 4;   // embed: 512 + 12800 words
    cudaFuncSetAttribute(mma_gemm<32, true, false>,
                         cudaFuncAttributeMaxDynamicSharedMemorySize, SMB_G1);
    cudaFuncSetAttribute(mma_gemm<48, false, false>,
                         cudaFuncAttributeMaxDynamicSharedMemorySize, SMB_G23);
    cudaFuncSetAttribute(mma_gemm<48, false, true>,
                         cudaFuncAttributeMaxDynamicSharedMemorySize, SMB_G23);
    cudaFuncSetAttribute(embed_kernel,
                         cudaFuncAttributeMaxDynamicSharedMemorySize, SMB_EMB);

    transpose_all_kernel<<<dim3(50, 8, 3), dim3(32, 8)>>>(
        fw0, fw1, fw2,
        (__nv_bfloat16*)pW1h, (__nv_bfloat16*)pW1l,
        (__nv_bfloat16*)pW2h, (__nv_bfloat16*)pW2l,
        (__nv_bfloat16*)pW3h, (__nv_bfloat16*)pW3l);
    build_tab_kernel<<<33, 128>>>(ew0, eb0, ew1, eb1, ew2, eb2);
    embed_kernel<<<ATOMS, 128, SMB_EMB>>>((const float4*)img);

    // launch index 3 (profiled slot): fused GEMM1, K=1600, BK=32
    mma_gemm<32, true, false><<<ATOMS / 32, NT, SMB_G1>>>(
        (const float*)pB, (const __nv_bfloat16*)pW1h, (const __nv_bfloat16*)pW1l,
        fb0, (float*)pH1, DRDIM, nullptr, nullptr, nullptr);
    mma_gemm<48, false, false><<<ATOMS / 32, NT, SMB_G23>>>(
        (const float*)pH1, (const __nv_bfloat16*)pW2h, (const __nv_bfloat16*)pW2l,
        fb1, (float*)pH2, F0, nullptr, nullptr, nullptr);
    mma_gemm<48, false, true><<<ATOMS / 32, NT, SMB_G23>>>(
        (const float*)pH2, (const __nv_bfloat16*)pW3h, (const __nv_bfloat16*)pW3l,
        fb2, nullptr, F0, fw3, fb3, out);

    etot_kernel<<<B_, 128>>>(out);
}